// round 3
// baseline (speedup 1.0000x reference)
#include <cuda_runtime.h>
#include <cstdint>

// Problem constants
#define H 512
#define W 512
#define NDET 512
#define NSAMP 512
#define NCH 32          // B*C = 4*8
#define HW (H * W)

// Channel-innermost transposed volume: xt[(y*W + x)*32 + c]
// 512*512*32 floats = 32 MB static device scratch (allocation-free rule).
__device__ static float g_xt[HW * NCH];

// ---------------------------------------------------------------------------
// Transpose (B,C,H,W) -> (H,W,BC) with coalesced reads AND writes via smem.
// Block: 256 threads handles 256 consecutive pixels for all 32 channels.
// ---------------------------------------------------------------------------
__global__ void transpose_kernel(const float* __restrict__ in) {
    __shared__ float tile[NCH][257];  // pad to keep both phases conflict-free
    const int tid = threadIdx.x;
    const int p0 = blockIdx.x * 256;

#pragma unroll
    for (int c = 0; c < NCH; ++c)
        tile[c][tid] = in[c * HW + p0 + tid];   // coalesced read
    __syncthreads();

#pragma unroll
    for (int it = 0; it < NCH; ++it) {
        int idx = it * 256 + tid;
        int pl = idx >> 5;          // pixel within block
        int c  = idx & 31;          // channel
        g_xt[(size_t)(p0 + pl) * NCH + c] = tile[c][pl];  // coalesced write
    }
}

// ---------------------------------------------------------------------------
// Radon forward projection.
// Warp = one (angle, detector) ray. Lane = (group g = lane>>3, li = lane&7).
// Group g handles samples s = g, g+4, g+8, ...; lane li covers channels
// 4*li .. 4*li+3 via one float4 load per corner (8 lanes * 16B = one 128B line).
// ---------------------------------------------------------------------------
__global__ __launch_bounds__(256) void radon_kernel(
    const float* __restrict__ angles, float* __restrict__ out, int A)
{
    const int a    = blockIdx.y;
    const int warp = threadIdx.x >> 5;
    const int lane = threadIdx.x & 31;
    const int t    = blockIdx.x * 8 + warp;     // detector index

    float ang = angles[a];
    float sn, cs;
    sincosf(ang, &sn, &cs);

    const float tv  = (float)t - 255.5f;
    const float xt0 = fmaf(tv, cs, 255.5f);     // cx + T*cos
    const float yt0 = fmaf(tv, sn, 255.5f);     // cy + T*sin
    const float nsn = -sn;

    const int g  = lane >> 3;
    const int li = lane & 7;
    const float4* __restrict__ base = reinterpret_cast<const float4*>(g_xt) + li;

    float4 acc = make_float4(0.f, 0.f, 0.f, 0.f);

    // 128 iterations per group; unroll 4 for MLP (16 outstanding LDG.128)
#pragma unroll 4
    for (int s = g; s < NSAMP; s += 4) {
        float sv = (float)s - 255.5f;
        float xs = fmaf(sv, nsn, xt0);
        float ys = fmaf(sv, cs, yt0);
        float fx = floorf(xs);
        float fy = floorf(ys);
        int   x0 = (int)fx;
        int   y0 = (int)fy;
        float wx = xs - fx;
        float wy = ys - fy;

        // reference: valid iff x0 in [0, W-2] and y0 in [0, H-2]
        bool valid = ((unsigned)x0 <= (unsigned)(W - 2)) &
                     ((unsigned)y0 <= (unsigned)(H - 2));
        int xc = min(max(x0, 0), W - 2);
        int yc = min(max(y0, 0), H - 2);

        // float4 offsets: +x -> +8 float4 (32 floats); +y -> +W*8 = 4096 float4
        const float4* p = base + ((yc << 9) + xc) * 8;
        float4 v00 = p[0];
        float4 v01 = p[8];
        float4 v10 = p[4096];
        float4 v11 = p[4104];

        float m = valid ? 1.0f : 0.0f;

        float top, bot, val;
        top = fmaf(wx, v01.x - v00.x, v00.x);
        bot = fmaf(wx, v11.x - v10.x, v10.x);
        val = fmaf(wy, bot - top, top);
        acc.x = fmaf(m, val, acc.x);

        top = fmaf(wx, v01.y - v00.y, v00.y);
        bot = fmaf(wx, v11.y - v10.y, v10.y);
        val = fmaf(wy, bot - top, top);
        acc.y = fmaf(m, val, acc.y);

        top = fmaf(wx, v01.z - v00.z, v00.z);
        bot = fmaf(wx, v11.z - v10.z, v10.z);
        val = fmaf(wy, bot - top, top);
        acc.z = fmaf(m, val, acc.z);

        top = fmaf(wx, v01.w - v00.w, v00.w);
        bot = fmaf(wx, v11.w - v10.w, v10.w);
        val = fmaf(wy, bot - top, top);
        acc.w = fmaf(m, val, acc.w);
    }

    // Combine the 4 s-phase partial sums (groups differ by lane bits 3,4)
#pragma unroll
    for (int m_ = 8; m_ <= 16; m_ <<= 1) {
        acc.x += __shfl_xor_sync(0xffffffffu, acc.x, m_);
        acc.y += __shfl_xor_sync(0xffffffffu, acc.y, m_);
        acc.z += __shfl_xor_sync(0xffffffffu, acc.z, m_);
        acc.w += __shfl_xor_sync(0xffffffffu, acc.w, m_);
    }

    if (lane < 8) {
        // channel bc = lane*4 + i ; out[(bc*A + a)*NDET + t]
        size_t chan_stride = (size_t)A * NDET;
        size_t o = ((size_t)(lane * 4) * A + a) * NDET + t;
        out[o]                   = acc.x;
        out[o + chan_stride]     = acc.y;
        out[o + 2 * chan_stride] = acc.z;
        out[o + 3 * chan_stride] = acc.w;
    }
}

extern "C" void kernel_launch(void* const* d_in, const int* in_sizes, int n_in,
                              void* d_out, int out_size)
{
    const float* x      = (const float*)d_in[0];   // (4,8,512,512) f32
    const float* angles = (const float*)d_in[1];   // (A,) f32
    float* out          = (float*)d_out;           // (4,8,A,512) f32
    const int A = in_sizes[1];

    transpose_kernel<<<HW / 256, 256>>>(x);

    dim3 grid(NDET / 8, A);
    radon_kernel<<<grid, 256>>>(angles, out, A);
}

// round 6
// speedup vs baseline: 1.3501x; 1.3501x over previous
#include <cuda_runtime.h>
#include <cuda_fp16.h>
#include <cstdint>

// Problem constants
#define H 512
#define W 512
#define NDET 512
#define NSAMP 512
#define NCH 32          // B*C = 4*8
#define HW (H * W)

// Duplicated pixel-pair, channel-interleaved fp16 volume.
// Line for (y, xp) = 128 bytes = 32 x half2 { v(y,xp,c), v(y,xp+1,c) }.
// Any bilinear x-pair (x0, x0+1) with x0 in [0,510] is ONE aligned 128B line.
// Size: 512*512 lines * 128 B = 32 MB static scratch.
__device__ static __half2 g_xt[HW * NCH];

// ---------------------------------------------------------------------------
// Pack kernel: (B,C,H,W) fp32 -> duplicated-pair interleaved fp16 lines.
// Grid: (4 segments, 512 rows). Block 256. Each block builds 128 lines of
// one image row (pairs xp in [X0, X0+128)), needing pixels [X0, X0+128].
// ---------------------------------------------------------------------------
__global__ void pack_kernel(const float* __restrict__ in) {
    __shared__ __half sh[130][NCH + 1];   // [pixel_local][channel], padded
    const int tid = threadIdx.x;
    const int seg = blockIdx.x;           // 0..3
    const int y   = blockIdx.y;           // 0..511
    const int X0  = seg * 128;

    // Load phase: 130 pixels x 32 channels, coalesced per channel.
    for (int c = 0; c < NCH; ++c) {
        if (tid < 130) {
            int px = X0 + tid;
            float v = (px < W) ? in[c * HW + y * W + px] : 0.0f;
            sh[tid][c] = __float2half(v);
        }
    }
    __syncthreads();

    // Write phase: 128 lines x 8 int4 = 1024 int4; thread does 4.
    int4* __restrict__ gout = reinterpret_cast<int4*>(g_xt);
#pragma unroll
    for (int k = 0; k < 4; ++k) {
        int id  = tid + k * 256;          // 0..1023
        int ll  = id >> 3;                // line local 0..127
        int jj  = id & 7;                 // int4 within line -> channels 4jj..4jj+3
        union { __half2 h[4]; int4 v; } u;
#pragma unroll
        for (int q = 0; q < 4; ++q)
            u.h[q] = __halves2half2(sh[ll][4 * jj + q], sh[ll + 1][4 * jj + q]);
        gout[(size_t)(y * W + X0 + ll) * 8 + jj] = u.v;
    }
}

// ---------------------------------------------------------------------------
// Radon forward projection.
// Warp = one (angle, detector) ray. lane = g*8+li; group g handles samples
// s = g, g+4, ...; lane li owns channels 4li..4li+3.
// Per sample: 2 LDG.128 (rows y0, y0+1), each one fully-utilized 128B line.
// ---------------------------------------------------------------------------
__global__ __launch_bounds__(256) void radon_kernel(
    const float* __restrict__ angles, float* __restrict__ out, int A)
{
    const int a    = blockIdx.y;
    const int warp = threadIdx.x >> 5;
    const int lane = threadIdx.x & 31;
    const int t    = blockIdx.x * 8 + warp;     // detector index

    float ang = angles[a];
    float sn, cs;
    sincosf(ang, &sn, &cs);

    const float tv  = (float)t - 255.5f;
    const float xt0 = fmaf(tv, cs, 255.5f);     // cx + T*cos
    const float yt0 = fmaf(tv, sn, 255.5f);     // cy + T*sin
    const float nsn = -sn;

    const int g  = lane >> 3;
    const int li = lane & 7;
    const int4* __restrict__ base = reinterpret_cast<const int4*>(g_xt) + li;

    float acc0 = 0.f, acc1 = 0.f, acc2 = 0.f, acc3 = 0.f;

#pragma unroll 4
    for (int s = g; s < NSAMP; s += 4) {
        float sv = (float)s - 255.5f;
        float xs = fmaf(sv, nsn, xt0);
        float ys = fmaf(sv, cs, yt0);
        float fx = floorf(xs);
        float fy = floorf(ys);
        int   x0 = (int)fx;
        int   y0 = (int)fy;
        float wx = xs - fx;
        float wy = ys - fy;

        // valid iff x0 in [0, W-2] and y0 in [0, H-2]
        bool valid = ((unsigned)x0 <= (unsigned)(W - 2)) &
                     ((unsigned)y0 <= (unsigned)(H - 2));
        int xc = min(max(x0, 0), W - 2);
        int yc = min(max(y0, 0), H - 2);
        float m = valid ? 1.0f : 0.0f;

        // Corner weights with mask folded in
        float am  = (1.0f - wy) * m;
        float bm  = wy * m;
        float omx = 1.0f - wx;
        float wlt = omx * am;   // (1-wx)(1-wy)m  -> left,  row y
        float wrt = wx  * am;   //   wx (1-wy)m  -> right, row y
        float wlb = omx * bm;   // (1-wx)  wy m  -> left,  row y+1
        float wrb = wx  * bm;   //   wx    wy m  -> right, row y+1

        int idx = ((yc << 9) + xc) * 8;     // int4 index of line start
        int4 rA = base[idx];                // row y   : ch 4li..4li+3, (L,R) half2
        int4 rB = base[idx + (W * 8)];      // row y+1

        const __half2* hA = reinterpret_cast<const __half2*>(&rA);
        const __half2* hB = reinterpret_cast<const __half2*>(&rB);

        float2 f;
        f = __half22float2(hA[0]); acc0 = fmaf(f.x, wlt, acc0); acc0 = fmaf(f.y, wrt, acc0);
        f = __half22float2(hA[1]); acc1 = fmaf(f.x, wlt, acc1); acc1 = fmaf(f.y, wrt, acc1);
        f = __half22float2(hA[2]); acc2 = fmaf(f.x, wlt, acc2); acc2 = fmaf(f.y, wrt, acc2);
        f = __half22float2(hA[3]); acc3 = fmaf(f.x, wlt, acc3); acc3 = fmaf(f.y, wrt, acc3);
        f = __half22float2(hB[0]); acc0 = fmaf(f.x, wlb, acc0); acc0 = fmaf(f.y, wrb, acc0);
        f = __half22float2(hB[1]); acc1 = fmaf(f.x, wlb, acc1); acc1 = fmaf(f.y, wrb, acc1);
        f = __half22float2(hB[2]); acc2 = fmaf(f.x, wlb, acc2); acc2 = fmaf(f.y, wrb, acc2);
        f = __half22float2(hB[3]); acc3 = fmaf(f.x, wlb, acc3); acc3 = fmaf(f.y, wrb, acc3);
    }

    // Reduce the 4 s-phase groups (lane bits 3,4)
#pragma unroll
    for (int m_ = 8; m_ <= 16; m_ <<= 1) {
        acc0 += __shfl_xor_sync(0xffffffffu, acc0, m_);
        acc1 += __shfl_xor_sync(0xffffffffu, acc1, m_);
        acc2 += __shfl_xor_sync(0xffffffffu, acc2, m_);
        acc3 += __shfl_xor_sync(0xffffffffu, acc3, m_);
    }

    // Lane (g, li) writes channel c = 4*li + g: one STG per lane.
    float v = (g == 0) ? acc0 : (g == 1) ? acc1 : (g == 2) ? acc2 : acc3;
    int c = 4 * li + g;
    out[(size_t)c * A * NDET + (size_t)a * NDET + t] = v;
}

extern "C" void kernel_launch(void* const* d_in, const int* in_sizes, int n_in,
                              void* d_out, int out_size)
{
    const float* x      = (const float*)d_in[0];   // (4,8,512,512) f32
    const float* angles = (const float*)d_in[1];   // (A,) f32
    float* out          = (float*)d_out;           // (4,8,A,512) f32
    const int A = in_sizes[1];

    dim3 pgrid(4, H);
    pack_kernel<<<pgrid, 256>>>(x);

    dim3 grid(NDET / 8, A);
    radon_kernel<<<grid, 256>>>(angles, out, A);
}

// round 7
// speedup vs baseline: 1.6814x; 1.2454x over previous
#include <cuda_runtime.h>
#include <cuda_fp16.h>
#include <cstdint>

// Problem constants
#define H 512
#define W 512
#define NDET 512
#define NSAMP 512
#define NCH 32          // B*C = 4*8
#define HW (H * W)

// Duplicated pixel-pair, channel-interleaved fp16 volume.
// Line for (y, xp) = 128 bytes = 32 x half2 { v(y,xp,c), v(y,xp+1,c) }.
// Any bilinear x-pair (x0, x0+1) with x0 in [0,510] is ONE aligned 128B line.
__device__ static __half2 g_xt[HW * NCH];

// ---------------------------------------------------------------------------
// Pack kernel: (B,C,H,W) fp32 -> duplicated-pair interleaved fp16 lines.
// ---------------------------------------------------------------------------
__global__ void pack_kernel(const float* __restrict__ in) {
    __shared__ __half sh[130][NCH + 1];   // [pixel_local][channel], padded
    const int tid = threadIdx.x;
    const int seg = blockIdx.x;           // 0..3
    const int y   = blockIdx.y;           // 0..511
    const int X0  = seg * 128;

    for (int c = 0; c < NCH; ++c) {
        if (tid < 130) {
            int px = X0 + tid;
            float v = (px < W) ? in[c * HW + y * W + px] : 0.0f;
            sh[tid][c] = __float2half(v);
        }
    }
    __syncthreads();

    int4* __restrict__ gout = reinterpret_cast<int4*>(g_xt);
#pragma unroll
    for (int k = 0; k < 4; ++k) {
        int id  = tid + k * 256;          // 0..1023
        int ll  = id >> 3;                // line local 0..127
        int jj  = id & 7;                 // int4 -> channels 4jj..4jj+3
        union { __half2 h[4]; int4 v; } u;
#pragma unroll
        for (int q = 0; q < 4; ++q)
            u.h[q] = __halves2half2(sh[ll][4 * jj + q], sh[ll + 1][4 * jj + q]);
        gout[(size_t)(y * W + X0 + ll) * 8 + jj] = u.v;
    }
}

// ---------------------------------------------------------------------------
// Radon forward projection.
// Warp = one (angle, detector) ray. lane = g*8+li; group g handles samples
// s = g, g+4, ...; lane li owns channels 4li..4li+3.
// y-interp done in fp16 SIMD (HSUB2+HFMA2); x-interp + accumulate in fp32.
// ---------------------------------------------------------------------------
__global__ __launch_bounds__(256) void radon_kernel(
    const float* __restrict__ angles, float* __restrict__ out, int A)
{
    const int a    = blockIdx.y;
    const int warp = threadIdx.x >> 5;
    const int lane = threadIdx.x & 31;
    const int t    = blockIdx.x * 8 + warp;     // detector index

    float ang = angles[a];
    float sn, cs;
    sincosf(ang, &sn, &cs);

    const float tv  = (float)t - 255.5f;
    const float xt0 = fmaf(tv, cs, 255.5f);     // cx + T*cos
    const float yt0 = fmaf(tv, sn, 255.5f);     // cy + T*sin
    const float nsn = -sn;

    const int g  = lane >> 3;
    const int li = lane & 7;
    const int4* __restrict__ base = reinterpret_cast<const int4*>(g_xt) + li;

    float acc0 = 0.f, acc1 = 0.f, acc2 = 0.f, acc3 = 0.f;

#pragma unroll 4
    for (int s = g; s < NSAMP; s += 4) {
        float sv = (float)s - 255.5f;
        float xs = fmaf(sv, nsn, xt0);
        float ys = fmaf(sv, cs, yt0);
        int   x0 = __float2int_rd(xs);          // floor as int, 1 cvt
        int   y0 = __float2int_rd(ys);
        float wx = xs - (float)x0;
        float wy = ys - (float)y0;

        // valid iff x0 in [0, W-2] and y0 in [0, H-2]
        bool valid = ((unsigned)x0 <= (unsigned)(W - 2)) &
                     ((unsigned)y0 <= (unsigned)(H - 2));

        // single clamp on the linear cell index (any in-range line is fine
        // when masked; both cell and cell+W lines must exist)
        int cell = y0 * W + x0;
        cell = min(max(cell, 0), HW - W - 1);

        const int4* p = base + cell * 8;
        int4 rA = p[0];                 // row y   : ch 4li..4li+3, (L,R) half2
        int4 rB = p[W * 8];             // row y+1

        __half2 wy2 = __float2half2_rn(wy);
        float omx = 1.0f - wx;
        float oxm = valid ? omx : 0.0f;   // left  weight (mask folded)
        float wxm = valid ? wx  : 0.0f;   // right weight

        const __half2* hA = reinterpret_cast<const __half2*>(&rA);
        const __half2* hB = reinterpret_cast<const __half2*>(&rB);

        __half2 d, ri;
        float2 f;
        d  = __hsub2(hB[0], hA[0]);
        ri = __hfma2(d, wy2, hA[0]);
        f  = __half22float2(ri);
        acc0 = fmaf(f.x, oxm, acc0); acc0 = fmaf(f.y, wxm, acc0);

        d  = __hsub2(hB[1], hA[1]);
        ri = __hfma2(d, wy2, hA[1]);
        f  = __half22float2(ri);
        acc1 = fmaf(f.x, oxm, acc1); acc1 = fmaf(f.y, wxm, acc1);

        d  = __hsub2(hB[2], hA[2]);
        ri = __hfma2(d, wy2, hA[2]);
        f  = __half22float2(ri);
        acc2 = fmaf(f.x, oxm, acc2); acc2 = fmaf(f.y, wxm, acc2);

        d  = __hsub2(hB[3], hA[3]);
        ri = __hfma2(d, wy2, hA[3]);
        f  = __half22float2(ri);
        acc3 = fmaf(f.x, oxm, acc3); acc3 = fmaf(f.y, wxm, acc3);
    }

    // Reduce the 4 s-phase groups (lane bits 3,4)
#pragma unroll
    for (int m_ = 8; m_ <= 16; m_ <<= 1) {
        acc0 += __shfl_xor_sync(0xffffffffu, acc0, m_);
        acc1 += __shfl_xor_sync(0xffffffffu, acc1, m_);
        acc2 += __shfl_xor_sync(0xffffffffu, acc2, m_);
        acc3 += __shfl_xor_sync(0xffffffffu, acc3, m_);
    }

    // Lane (g, li) writes channel c = 4*li + g: one STG per lane.
    float v = (g == 0) ? acc0 : (g == 1) ? acc1 : (g == 2) ? acc2 : acc3;
    int c = 4 * li + g;
    out[(size_t)c * A * NDET + (size_t)a * NDET + t] = v;
}

extern "C" void kernel_launch(void* const* d_in, const int* in_sizes, int n_in,
                              void* d_out, int out_size)
{
    const float* x      = (const float*)d_in[0];   // (4,8,512,512) f32
    const float* angles = (const float*)d_in[1];   // (A,) f32
    float* out          = (float*)d_out;           // (4,8,A,512) f32
    const int A = in_sizes[1];

    dim3 pgrid(4, H);
    pack_kernel<<<pgrid, 256>>>(x);

    dim3 grid(NDET / 8, A);
    radon_kernel<<<grid, 256>>>(angles, out, A);
}

// round 8
// speedup vs baseline: 1.8642x; 1.1087x over previous
#include <cuda_runtime.h>
#include <cuda_fp16.h>
#include <cstdint>

// Problem constants
#define H 512
#define W 512
#define NDET 512
#define NSAMP 512
#define NCH 32          // B*C = 4*8
#define HW (H * W)

// Duplicated pixel-pair, channel-interleaved fp16 volume.
// Line for (y, xp) = 128 bytes = 32 x half2 { v(y,xp,c), v(y,xp+1,c) }.
__device__ static __half2 g_xt[HW * NCH];

// ---------------------------------------------------------------------------
// Pack kernel: (B,C,H,W) fp32 -> duplicated-pair interleaved fp16 lines.
// ---------------------------------------------------------------------------
__global__ void pack_kernel(const float* __restrict__ in) {
    __shared__ __half sh[130][NCH + 1];
    const int tid = threadIdx.x;
    const int seg = blockIdx.x;           // 0..3
    const int y   = blockIdx.y;           // 0..511
    const int X0  = seg * 128;

    for (int c = 0; c < NCH; ++c) {
        if (tid < 130) {
            int px = X0 + tid;
            float v = (px < W) ? in[c * HW + y * W + px] : 0.0f;
            sh[tid][c] = __float2half(v);
        }
    }
    __syncthreads();

    int4* __restrict__ gout = reinterpret_cast<int4*>(g_xt);
#pragma unroll
    for (int k = 0; k < 4; ++k) {
        int id  = tid + k * 256;
        int ll  = id >> 3;
        int jj  = id & 7;
        union { __half2 h[4]; int4 v; } u;
#pragma unroll
        for (int q = 0; q < 4; ++q)
            u.h[q] = __halves2half2(sh[ll][4 * jj + q], sh[ll + 1][4 * jj + q]);
        gout[(size_t)(y * W + X0 + ll) * 8 + jj] = u.v;
    }
}

// Exact in-loop validity predicate (must match loop arithmetic bit-for-bit).
__device__ __forceinline__ bool valid_s(int s, float nsn, float cs,
                                        float xt0, float yt0) {
    float sv = (float)s - 255.5f;
    float xs = fmaf(sv, nsn, xt0);
    float ys = fmaf(sv, cs, yt0);
    int x0 = __float2int_rd(xs);
    int y0 = __float2int_rd(ys);
    return ((unsigned)x0 <= (unsigned)(W - 2)) &
           ((unsigned)y0 <= (unsigned)(H - 2));
}

// ---------------------------------------------------------------------------
// Radon forward projection.
// Warp = one (angle, detector) ray. lane = g*8+li; group g handles samples
// s ≡ g (mod 4); lane li owns channels 4li..4li+3 (one int4 per row-line).
// Valid-s interval computed once per ray -> no per-sample mask.
// y-interp fp16 SIMD; x-interp via packed fma.rn.f32x2 into (L,R) pair accs.
// ---------------------------------------------------------------------------
__global__ __launch_bounds__(256) void radon_kernel(
    const float* __restrict__ angles, float* __restrict__ out, int A)
{
    const int a    = blockIdx.y;
    const int warp = threadIdx.x >> 5;
    const int lane = threadIdx.x & 31;
    const int t    = blockIdx.x * 8 + warp;     // detector index

    float ang = angles[a];
    float sn, cs;
    sincosf(ang, &sn, &cs);

    const float tv  = (float)t - 255.5f;
    const float xt0 = fmaf(tv, cs, 255.5f);
    const float yt0 = fmaf(tv, sn, 255.5f);
    const float nsn = -sn;

    // ---- valid s-interval for this ray (warp-uniform) ----
    float lo = -1e9f, hi = 1e9f;
    // constraint: xt0 + nsn*sv in [0, 511)
    if (nsn > 0.f)      { lo = fmaxf(lo, (0.f   - xt0) / nsn);
                          hi = fminf(hi, (511.f - xt0) / nsn); }
    else if (nsn < 0.f) { lo = fmaxf(lo, (511.f - xt0) / nsn);
                          hi = fminf(hi, (0.f   - xt0) / nsn); }
    else if (!(xt0 >= 0.f && xt0 < 511.f)) { lo = 1.f; hi = 0.f; }
    // constraint: yt0 + cs*sv in [0, 511)
    if (cs > 0.f)       { lo = fmaxf(lo, (0.f   - yt0) / cs);
                          hi = fminf(hi, (511.f - yt0) / cs); }
    else if (cs < 0.f)  { lo = fmaxf(lo, (511.f - yt0) / cs);
                          hi = fminf(hi, (0.f   - yt0) / cs); }
    else if (!(yt0 >= 0.f && yt0 < 511.f)) { lo = 1.f; hi = 0.f; }

    lo = fmaxf(lo, -300.f);  hi = fminf(hi, 300.f);
    int s_lo = max(0,   (int)floorf(lo + 255.5f) - 2);
    int s_hi = min(511, (int)ceilf (hi + 255.5f) + 2);
    // exact fix-up against the in-loop predicate
    while (s_lo <= s_hi && !valid_s(s_lo, nsn, cs, xt0, yt0)) ++s_lo;
    while (s_lo <= s_hi && !valid_s(s_hi, nsn, cs, xt0, yt0)) --s_hi;

    const int g  = lane >> 3;
    const int li = lane & 7;
    const int4* __restrict__ base = reinterpret_cast<const int4*>(g_xt) + li;

    // packed (left, right) fp32 accumulators per channel
    unsigned long long ap0 = 0ull, ap1 = 0ull, ap2 = 0ull, ap3 = 0ull;

    int s0 = s_lo + ((g - s_lo) & 3);   // first s >= s_lo with s == g (mod 4)
    float sv = (float)s0 - 255.5f;      // exact; sv += 4.0f stays exact

#pragma unroll 4
    for (int s = s0; s <= s_hi; s += 4, sv += 4.0f) {
        float xs = fmaf(sv, nsn, xt0);
        float ys = fmaf(sv, cs, yt0);
        int   x0 = __float2int_rd(xs);
        int   y0 = __float2int_rd(ys);
        float wx = xs - (float)x0;
        float wy = ys - (float)y0;

        // interval guarantees validity; clamp is memory-safety insurance only
        int cell = y0 * W + x0;
        cell = min(max(cell, 0), HW - W - 1);

        const int4* p = base + cell * 8;
        int4 rA = p[0];                 // row y   : ch 4li..4li+3, (L,R) half2
        int4 rB = p[W * 8];             // row y+1

        __half2 wy2 = __float2half2_rn(wy);
        float omx = 1.0f - wx;
        unsigned long long w64;
        asm("mov.b64 %0, {%1, %2};" : "=l"(w64) : "f"(omx), "f"(wx));

        const __half2* hA = reinterpret_cast<const __half2*>(&rA);
        const __half2* hB = reinterpret_cast<const __half2*>(&rB);

        __half2 d, ri;
        float2 f;
        unsigned long long v64;

        d = __hsub2(hB[0], hA[0]); ri = __hfma2(d, wy2, hA[0]);
        f = __half22float2(ri);
        asm("mov.b64 %0, {%1, %2};" : "=l"(v64) : "f"(f.x), "f"(f.y));
        asm("fma.rn.f32x2 %0, %1, %2, %0;" : "+l"(ap0) : "l"(v64), "l"(w64));

        d = __hsub2(hB[1], hA[1]); ri = __hfma2(d, wy2, hA[1]);
        f = __half22float2(ri);
        asm("mov.b64 %0, {%1, %2};" : "=l"(v64) : "f"(f.x), "f"(f.y));
        asm("fma.rn.f32x2 %0, %1, %2, %0;" : "+l"(ap1) : "l"(v64), "l"(w64));

        d = __hsub2(hB[2], hA[2]); ri = __hfma2(d, wy2, hA[2]);
        f = __half22float2(ri);
        asm("mov.b64 %0, {%1, %2};" : "=l"(v64) : "f"(f.x), "f"(f.y));
        asm("fma.rn.f32x2 %0, %1, %2, %0;" : "+l"(ap2) : "l"(v64), "l"(w64));

        d = __hsub2(hB[3], hA[3]); ri = __hfma2(d, wy2, hA[3]);
        f = __half22float2(ri);
        asm("mov.b64 %0, {%1, %2};" : "=l"(v64) : "f"(f.x), "f"(f.y));
        asm("fma.rn.f32x2 %0, %1, %2, %0;" : "+l"(ap3) : "l"(v64), "l"(w64));
    }

    // unpack packed (L,R) accumulators and combine
    float aL, aR;
    float acc0, acc1, acc2, acc3;
    asm("mov.b64 {%0, %1}, %2;" : "=f"(aL), "=f"(aR) : "l"(ap0)); acc0 = aL + aR;
    asm("mov.b64 {%0, %1}, %2;" : "=f"(aL), "=f"(aR) : "l"(ap1)); acc1 = aL + aR;
    asm("mov.b64 {%0, %1}, %2;" : "=f"(aL), "=f"(aR) : "l"(ap2)); acc2 = aL + aR;
    asm("mov.b64 {%0, %1}, %2;" : "=f"(aL), "=f"(aR) : "l"(ap3)); acc3 = aL + aR;

    // Reduce the 4 s-phase groups (lane bits 3,4)
#pragma unroll
    for (int m_ = 8; m_ <= 16; m_ <<= 1) {
        acc0 += __shfl_xor_sync(0xffffffffu, acc0, m_);
        acc1 += __shfl_xor_sync(0xffffffffu, acc1, m_);
        acc2 += __shfl_xor_sync(0xffffffffu, acc2, m_);
        acc3 += __shfl_xor_sync(0xffffffffu, acc3, m_);
    }

    // Lane (g, li) writes channel c = 4*li + g.
    float v = (g == 0) ? acc0 : (g == 1) ? acc1 : (g == 2) ? acc2 : acc3;
    int c = 4 * li + g;
    out[(size_t)c * A * NDET + (size_t)a * NDET + t] = v;
}

extern "C" void kernel_launch(void* const* d_in, const int* in_sizes, int n_in,
                              void* d_out, int out_size)
{
    const float* x      = (const float*)d_in[0];   // (4,8,512,512) f32
    const float* angles = (const float*)d_in[1];   // (A,) f32
    float* out          = (float*)d_out;           // (4,8,A,512) f32
    const int A = in_sizes[1];

    dim3 pgrid(4, H);
    pack_kernel<<<pgrid, 256>>>(x);

    dim3 grid(NDET / 8, A);
    radon_kernel<<<grid, 256>>>(angles, out, A);
}

// round 9
// speedup vs baseline: 1.8960x; 1.0171x over previous
#include <cuda_runtime.h>
#include <cuda_fp16.h>
#include <cstdint>

// Problem constants
#define H 512
#define W 512
#define NDET 512
#define NSAMP 512
#define NCH 32          // B*C = 4*8
#define HW (H * W)

// Duplicated pixel-pair, channel-interleaved fp16 volume.
// Line for (y, xp) = 128 bytes = 32 x half2 { v(y,xp,c), v(y,xp+1,c) }.
__device__ static __half2 g_xt[HW * NCH];

// ---------------------------------------------------------------------------
// Pack kernel: (B,C,H,W) fp32 -> duplicated-pair interleaved fp16 lines.
// ---------------------------------------------------------------------------
__global__ void pack_kernel(const float* __restrict__ in) {
    __shared__ __half sh[130][NCH + 1];
    const int tid = threadIdx.x;
    const int seg = blockIdx.x;           // 0..3
    const int y   = blockIdx.y;           // 0..511
    const int X0  = seg * 128;

    for (int c = 0; c < NCH; ++c) {
        if (tid < 130) {
            int px = X0 + tid;
            float v = (px < W) ? in[c * HW + y * W + px] : 0.0f;
            sh[tid][c] = __float2half(v);
        }
    }
    __syncthreads();

    int4* __restrict__ gout = reinterpret_cast<int4*>(g_xt);
#pragma unroll
    for (int k = 0; k < 4; ++k) {
        int id  = tid + k * 256;
        int ll  = id >> 3;
        int jj  = id & 7;
        union { __half2 h[4]; int4 v; } u;
#pragma unroll
        for (int q = 0; q < 4; ++q)
            u.h[q] = __halves2half2(sh[ll][4 * jj + q], sh[ll + 1][4 * jj + q]);
        gout[(size_t)(y * W + X0 + ll) * 8 + jj] = u.v;
    }
}

// Exact in-loop validity predicate (must match loop arithmetic bit-for-bit).
__device__ __forceinline__ bool valid_s(int s, float nsn, float cs,
                                        float xt0, float yt0) {
    float sv = (float)s - 255.5f;
    float xs = fmaf(sv, nsn, xt0);
    float ys = fmaf(sv, cs, yt0);
    int x0 = __float2int_rd(xs);
    int y0 = __float2int_rd(ys);
    return ((unsigned)x0 <= (unsigned)(W - 2)) &
           ((unsigned)y0 <= (unsigned)(H - 2));
}

// ---------------------------------------------------------------------------
// Radon forward projection.
// Warp = one (angle, detector) ray. lane = g*8+li; group g handles samples
// s ≡ g (mod 4); lane li owns channels 4li..4li+3 (one int4 per row-line).
// Valid-s interval once per ray (monotonicity => interior needs no clamp).
// y-interp fp16 SIMD; x-interp via packed fma.rn.f32x2 into (L,R) pair accs.
// ---------------------------------------------------------------------------
__global__ __launch_bounds__(256, 7) void radon_kernel(
    const float* __restrict__ angles, float* __restrict__ out, int A)
{
    const int a    = blockIdx.y;
    const int warp = threadIdx.x >> 5;
    const int lane = threadIdx.x & 31;
    const int t    = blockIdx.x * 8 + warp;     // detector index

    float ang = angles[a];
    float sn, cs;
    sincosf(ang, &sn, &cs);

    const float tv  = (float)t - 255.5f;
    const float xt0 = fmaf(tv, cs, 255.5f);
    const float yt0 = fmaf(tv, sn, 255.5f);
    const float nsn = -sn;

    // ---- valid s-interval for this ray (warp-uniform) ----
    float lo = -1e9f, hi = 1e9f;
    if (nsn > 0.f)      { lo = fmaxf(lo, (0.f   - xt0) / nsn);
                          hi = fminf(hi, (511.f - xt0) / nsn); }
    else if (nsn < 0.f) { lo = fmaxf(lo, (511.f - xt0) / nsn);
                          hi = fminf(hi, (0.f   - xt0) / nsn); }
    else if (!(xt0 >= 0.f && xt0 < 511.f)) { lo = 1.f; hi = 0.f; }
    if (cs > 0.f)       { lo = fmaxf(lo, (0.f   - yt0) / cs);
                          hi = fminf(hi, (511.f - yt0) / cs); }
    else if (cs < 0.f)  { lo = fmaxf(lo, (511.f - yt0) / cs);
                          hi = fminf(hi, (0.f   - yt0) / cs); }
    else if (!(yt0 >= 0.f && yt0 < 511.f)) { lo = 1.f; hi = 0.f; }

    lo = fmaxf(lo, -300.f);  hi = fminf(hi, 300.f);
    int s_lo = max(0,   (int)floorf(lo + 255.5f) - 2);
    int s_hi = min(511, (int)ceilf (hi + 255.5f) + 2);
    // exact fix-up against the in-loop predicate; monotone coords =>
    // every interior s is then valid (no per-sample clamp needed).
    while (s_lo <= s_hi && !valid_s(s_lo, nsn, cs, xt0, yt0)) ++s_lo;
    while (s_lo <= s_hi && !valid_s(s_hi, nsn, cs, xt0, yt0)) --s_hi;

    const int g  = lane >> 3;
    const int li = lane & 7;
    const int4* __restrict__ base = reinterpret_cast<const int4*>(g_xt) + li;

    // packed (left, right) fp32 accumulators per channel
    unsigned long long ap0 = 0ull, ap1 = 0ull, ap2 = 0ull, ap3 = 0ull;

    int s0 = s_lo + ((g - s_lo) & 3);   // first s >= s_lo with s == g (mod 4)
    float sv = (float)s0 - 255.5f;      // exact; sv += 4.0f stays exact

#pragma unroll 2
    for (int s = s0; s <= s_hi; s += 4, sv += 4.0f) {
        float xs = fmaf(sv, nsn, xt0);
        float ys = fmaf(sv, cs, yt0);
        int   x0 = __float2int_rd(xs);
        int   y0 = __float2int_rd(ys);
        float wx = xs - (float)x0;
        float wy = ys - (float)y0;

        int cell = y0 * W + x0;         // guaranteed in-bounds (see above)

        const int4* p = base + cell * 8;
        int4 rA = p[0];                 // row y   : ch 4li..4li+3, (L,R) half2
        int4 rB = p[W * 8];             // row y+1

        __half2 wy2 = __float2half2_rn(wy);
        float omx = 1.0f - wx;
        unsigned long long w64;
        asm("mov.b64 %0, {%1, %2};" : "=l"(w64) : "f"(omx), "f"(wx));

        const __half2* hA = reinterpret_cast<const __half2*>(&rA);
        const __half2* hB = reinterpret_cast<const __half2*>(&rB);

        __half2 d, ri;
        float2 f;
        unsigned long long v64;

        d = __hsub2(hB[0], hA[0]); ri = __hfma2(d, wy2, hA[0]);
        f = __half22float2(ri);
        asm("mov.b64 %0, {%1, %2};" : "=l"(v64) : "f"(f.x), "f"(f.y));
        asm("fma.rn.f32x2 %0, %1, %2, %0;" : "+l"(ap0) : "l"(v64), "l"(w64));

        d = __hsub2(hB[1], hA[1]); ri = __hfma2(d, wy2, hA[1]);
        f = __half22float2(ri);
        asm("mov.b64 %0, {%1, %2};" : "=l"(v64) : "f"(f.x), "f"(f.y));
        asm("fma.rn.f32x2 %0, %1, %2, %0;" : "+l"(ap1) : "l"(v64), "l"(w64));

        d = __hsub2(hB[2], hA[2]); ri = __hfma2(d, wy2, hA[2]);
        f = __half22float2(ri);
        asm("mov.b64 %0, {%1, %2};" : "=l"(v64) : "f"(f.x), "f"(f.y));
        asm("fma.rn.f32x2 %0, %1, %2, %0;" : "+l"(ap2) : "l"(v64), "l"(w64));

        d = __hsub2(hB[3], hA[3]); ri = __hfma2(d, wy2, hA[3]);
        f = __half22float2(ri);
        asm("mov.b64 %0, {%1, %2};" : "=l"(v64) : "f"(f.x), "f"(f.y));
        asm("fma.rn.f32x2 %0, %1, %2, %0;" : "+l"(ap3) : "l"(v64), "l"(w64));
    }

    // unpack packed (L,R) accumulators and combine
    float aL, aR;
    float acc0, acc1, acc2, acc3;
    asm("mov.b64 {%0, %1}, %2;" : "=f"(aL), "=f"(aR) : "l"(ap0)); acc0 = aL + aR;
    asm("mov.b64 {%0, %1}, %2;" : "=f"(aL), "=f"(aR) : "l"(ap1)); acc1 = aL + aR;
    asm("mov.b64 {%0, %1}, %2;" : "=f"(aL), "=f"(aR) : "l"(ap2)); acc2 = aL + aR;
    asm("mov.b64 {%0, %1}, %2;" : "=f"(aL), "=f"(aR) : "l"(ap3)); acc3 = aL + aR;

    // Reduce the 4 s-phase groups (lane bits 3,4)
#pragma unroll
    for (int m_ = 8; m_ <= 16; m_ <<= 1) {
        acc0 += __shfl_xor_sync(0xffffffffu, acc0, m_);
        acc1 += __shfl_xor_sync(0xffffffffu, acc1, m_);
        acc2 += __shfl_xor_sync(0xffffffffu, acc2, m_);
        acc3 += __shfl_xor_sync(0xffffffffu, acc3, m_);
    }

    // Lane (g, li) writes channel c = 4*li + g.
    float v = (g == 0) ? acc0 : (g == 1) ? acc1 : (g == 2) ? acc2 : acc3;
    int c = 4 * li + g;
    out[(size_t)c * A * NDET + (size_t)a * NDET + t] = v;
}

extern "C" void kernel_launch(void* const* d_in, const int* in_sizes, int n_in,
                              void* d_out, int out_size)
{
    const float* x      = (const float*)d_in[0];   // (4,8,512,512) f32
    const float* angles = (const float*)d_in[1];   // (A,) f32
    float* out          = (float*)d_out;           // (4,8,A,512) f32
    const int A = in_sizes[1];

    dim3 pgrid(4, H);
    pack_kernel<<<pgrid, 256>>>(x);

    dim3 grid(NDET / 8, A);
    radon_kernel<<<grid, 256>>>(angles, out, A);
}

// round 11
// speedup vs baseline: 1.9397x; 1.0231x over previous
#include <cuda_runtime.h>
#include <cuda_fp16.h>
#include <cstdint>

// Problem constants
#define H 512
#define W 512
#define NDET 512
#define NSAMP 512
#define NCH 32          // B*C = 4*8
#define HW (H * W)

// Duplicated pixel-pair, channel-interleaved fp16 volume.
// Line for (y, xp) = 128 bytes = 32 x half2 { v(y,xp,c), v(y,xp+1,c) }.
__device__ static __half2 g_xt[HW * NCH];

// ---------------------------------------------------------------------------
// Pack kernel: (B,C,H,W) fp32 -> duplicated-pair interleaved fp16 lines.
// ---------------------------------------------------------------------------
__global__ void pack_kernel(const float* __restrict__ in) {
    __shared__ __half sh[130][NCH + 1];
    const int tid = threadIdx.x;
    const int seg = blockIdx.x;           // 0..3
    const int y   = blockIdx.y;           // 0..511
    const int X0  = seg * 128;

    for (int c = 0; c < NCH; ++c) {
        if (tid < 130) {
            int px = X0 + tid;
            float v = (px < W) ? in[c * HW + y * W + px] : 0.0f;
            sh[tid][c] = __float2half(v);
        }
    }
    __syncthreads();

    int4* __restrict__ gout = reinterpret_cast<int4*>(g_xt);
#pragma unroll
    for (int k = 0; k < 4; ++k) {
        int id  = tid + k * 256;
        int ll  = id >> 3;
        int jj  = id & 7;
        union { __half2 h[4]; int4 v; } u;
#pragma unroll
        for (int q = 0; q < 4; ++q)
            u.h[q] = __halves2half2(sh[ll][4 * jj + q], sh[ll + 1][4 * jj + q]);
        gout[(size_t)(y * W + X0 + ll) * 8 + jj] = u.v;
    }
}

// Exact in-loop validity predicate (must match loop arithmetic bit-for-bit).
__device__ __forceinline__ bool valid_s(int s, float nsn, float cs,
                                        float xt0, float yt0) {
    float sv = (float)s - 255.5f;
    float xs = fmaf(sv, nsn, xt0);
    float ys = fmaf(sv, cs, yt0);
    int x0 = __float2int_rd(xs);
    int y0 = __float2int_rd(ys);
    return ((unsigned)x0 <= (unsigned)(W - 2)) &
           ((unsigned)y0 <= (unsigned)(H - 2));
}

// ---------------------------------------------------------------------------
// Radon forward projection.
// Warp = one (angle, detector) ray. lane = g*8+li; group g handles samples
// s ≡ g (mod 4); lane li owns channels 4li..4li+3 (one int4 per row-line).
// Valid-s interval once per ray (monotonicity => interior needs no clamp).
// y-interp fp16 SIMD; x-interp via packed fma.rn.f32x2 into (L,R) pair accs.
// launch_bounds(256,6): 42-reg budget so ptxas can batch 4 LDGs (MLP 8)
// while keeping 6 blocks (75% occ) resident.
// ---------------------------------------------------------------------------
__global__ __launch_bounds__(256, 6) void radon_kernel(
    const float* __restrict__ angles, float* __restrict__ out, int A)
{
    const int a    = blockIdx.y;
    const int warp = threadIdx.x >> 5;
    const int lane = threadIdx.x & 31;
    const int t    = blockIdx.x * 8 + warp;     // detector index

    float ang = angles[a];
    float sn, cs;
    sincosf(ang, &sn, &cs);

    const float tv  = (float)t - 255.5f;
    const float xt0 = fmaf(tv, cs, 255.5f);
    const float yt0 = fmaf(tv, sn, 255.5f);
    const float nsn = -sn;

    // ---- valid s-interval for this ray (warp-uniform) ----
    float lo = -1e9f, hi = 1e9f;
    if (nsn > 0.f)      { lo = fmaxf(lo, (0.f   - xt0) / nsn);
                          hi = fminf(hi, (511.f - xt0) / nsn); }
    else if (nsn < 0.f) { lo = fmaxf(lo, (511.f - xt0) / nsn);
                          hi = fminf(hi, (0.f   - xt0) / nsn); }
    else if (!(xt0 >= 0.f && xt0 < 511.f)) { lo = 1.f; hi = 0.f; }
    if (cs > 0.f)       { lo = fmaxf(lo, (0.f   - yt0) / cs);
                          hi = fminf(hi, (511.f - yt0) / cs); }
    else if (cs < 0.f)  { lo = fmaxf(lo, (511.f - yt0) / cs);
                          hi = fminf(hi, (0.f   - yt0) / cs); }
    else if (!(yt0 >= 0.f && yt0 < 511.f)) { lo = 1.f; hi = 0.f; }

    lo = fmaxf(lo, -300.f);  hi = fminf(hi, 300.f);
    int s_lo = max(0,   (int)floorf(lo + 255.5f) - 2);
    int s_hi = min(511, (int)ceilf (hi + 255.5f) + 2);
    // exact fix-up against the in-loop predicate; monotone coords =>
    // every interior s is then valid (no per-sample clamp needed).
    while (s_lo <= s_hi && !valid_s(s_lo, nsn, cs, xt0, yt0)) ++s_lo;
    while (s_lo <= s_hi && !valid_s(s_hi, nsn, cs, xt0, yt0)) --s_hi;

    const int g  = lane >> 3;
    const int li = lane & 7;
    const int4* __restrict__ base = reinterpret_cast<const int4*>(g_xt) + li;

    // packed (left, right) fp32 accumulators per channel
    unsigned long long ap0 = 0ull, ap1 = 0ull, ap2 = 0ull, ap3 = 0ull;

    int s0 = s_lo + ((g - s_lo) & 3);   // first s >= s_lo with s == g (mod 4)
    float sv = (float)s0 - 255.5f;      // exact; sv += 4.0f stays exact

#pragma unroll 4
    for (int s = s0; s <= s_hi; s += 4, sv += 4.0f) {
        float xs = fmaf(sv, nsn, xt0);
        float ys = fmaf(sv, cs, yt0);
        int   x0 = __float2int_rd(xs);
        int   y0 = __float2int_rd(ys);
        float wx = xs - (float)x0;
        float wy = ys - (float)y0;

        int cell = y0 * W + x0;         // guaranteed in-bounds (see above)

        const int4* p = base + cell * 8;
        int4 rA = p[0];                 // row y   : ch 4li..4li+3, (L,R) half2
        int4 rB = p[W * 8];             // row y+1

        __half2 wy2 = __float2half2_rn(wy);
        float omx = 1.0f - wx;
        unsigned long long w64;
        asm("mov.b64 %0, {%1, %2};" : "=l"(w64) : "f"(omx), "f"(wx));

        const __half2* hA = reinterpret_cast<const __half2*>(&rA);
        const __half2* hB = reinterpret_cast<const __half2*>(&rB);

        __half2 d, ri;
        float2 f;
        unsigned long long v64;

        d = __hsub2(hB[0], hA[0]); ri = __hfma2(d, wy2, hA[0]);
        f = __half22float2(ri);
        asm("mov.b64 %0, {%1, %2};" : "=l"(v64) : "f"(f.x), "f"(f.y));
        asm("fma.rn.f32x2 %0, %1, %2, %0;" : "+l"(ap0) : "l"(v64), "l"(w64));

        d = __hsub2(hB[1], hA[1]); ri = __hfma2(d, wy2, hA[1]);
        f = __half22float2(ri);
        asm("mov.b64 %0, {%1, %2};" : "=l"(v64) : "f"(f.x), "f"(f.y));
        asm("fma.rn.f32x2 %0, %1, %2, %0;" : "+l"(ap1) : "l"(v64), "l"(w64));

        d = __hsub2(hB[2], hA[2]); ri = __hfma2(d, wy2, hA[2]);
        f = __half22float2(ri);
        asm("mov.b64 %0, {%1, %2};" : "=l"(v64) : "f"(f.x), "f"(f.y));
        asm("fma.rn.f32x2 %0, %1, %2, %0;" : "+l"(ap2) : "l"(v64), "l"(w64));

        d = __hsub2(hB[3], hA[3]); ri = __hfma2(d, wy2, hA[3]);
        f = __half22float2(ri);
        asm("mov.b64 %0, {%1, %2};" : "=l"(v64) : "f"(f.x), "f"(f.y));
        asm("fma.rn.f32x2 %0, %1, %2, %0;" : "+l"(ap3) : "l"(v64), "l"(w64));
    }

    // unpack packed (L,R) accumulators and combine
    float aL, aR;
    float acc0, acc1, acc2, acc3;
    asm("mov.b64 {%0, %1}, %2;" : "=f"(aL), "=f"(aR) : "l"(ap0)); acc0 = aL + aR;
    asm("mov.b64 {%0, %1}, %2;" : "=f"(aL), "=f"(aR) : "l"(ap1)); acc1 = aL + aR;
    asm("mov.b64 {%0, %1}, %2;" : "=f"(aL), "=f"(aR) : "l"(ap2)); acc2 = aL + aR;
    asm("mov.b64 {%0, %1}, %2;" : "=f"(aL), "=f"(aR) : "l"(ap3)); acc3 = aL + aR;

    // Reduce the 4 s-phase groups (lane bits 3,4)
#pragma unroll
    for (int m_ = 8; m_ <= 16; m_ <<= 1) {
        acc0 += __shfl_xor_sync(0xffffffffu, acc0, m_);
        acc1 += __shfl_xor_sync(0xffffffffu, acc1, m_);
        acc2 += __shfl_xor_sync(0xffffffffu, acc2, m_);
        acc3 += __shfl_xor_sync(0xffffffffu, acc3, m_);
    }

    // Lane (g, li) writes channel c = 4*li + g.
    float v = (g == 0) ? acc0 : (g == 1) ? acc1 : (g == 2) ? acc2 : acc3;
    int c = 4 * li + g;
    out[(size_t)c * A * NDET + (size_t)a * NDET + t] = v;
}

extern "C" void kernel_launch(void* const* d_in, const int* in_sizes, int n_in,
                              void* d_out, int out_size)
{
    const float* x      = (const float*)d_in[0];   // (4,8,512,512) f32
    const float* angles = (const float*)d_in[1];   // (A,) f32
    float* out          = (float*)d_out;           // (4,8,A,512) f32
    const int A = in_sizes[1];

    dim3 pgrid(4, H);
    pack_kernel<<<pgrid, 256>>>(x);

    dim3 grid(NDET / 8, A);
    radon_kernel<<<grid, 256>>>(angles, out, A);
}